// round 15
// baseline (speedup 1.0000x reference)
#include <cuda_runtime.h>
#include <cuda_fp16.h>
#include <cuda_bf16.h>
#include <cstdint>

#define N_NODES 50000
#define IN_DIM  1000
#define HIDDEN  256
#define OUT_DIM 2
#define MAX_ENTRIES 1700000

// ---------------- scratch ----------------
__device__ __align__(16) __half g_xh[(long long)N_NODES * IN_DIM];  // x in fp16
__device__ __align__(16) __half g_w1h[HIDDEN * IN_DIM];             // W1^T fp16 [n][k]
__device__ __align__(16) __half g_h1h[N_NODES * HIDDEN];            // x@W1 fp16
__device__ __align__(16) float  g_h2[N_NODES * OUT_DIM];
__device__ int   g_deg[N_NODES];
__device__ int   g_off[N_NODES + 1];
__device__ int   g_cursor[N_NODES];
__device__ float g_dinv[N_NODES];
__device__ int   g_csr_src[MAX_ENTRIES];
__device__ float g_csr_norm[MAX_ENTRIES];
__device__ int   g_is64;
__device__ int   g_bsum[64];

// ---------------- dtype detect ----------------
__global__ void k_detect(const int* __restrict__ ei32, int n_words) {
    __shared__ int nz;
    if (threadIdx.x == 0) nz = 0;
    __syncthreads();
    for (int i = threadIdx.x; i < 32768; i += blockDim.x) {
        int w = 1 + 96 * i;
        if (w < n_words && ei32[w] != 0) nz = 1;
    }
    __syncthreads();
    if (threadIdx.x == 0) g_is64 = (nz == 0) ? 1 : 0;
}

__device__ __forceinline__ int load_edge(const void* ei, int pos) {
    int v;
    if (g_is64) v = (int)((const long long*)ei)[pos];
    else        v = ((const int*)ei)[pos];
    return min(max(v, 0), N_NODES - 1);
}

// ---------------- x -> fp16 ----------------
__global__ void k_cvtx(const float4* __restrict__ x4, int n4) {
    int i = blockIdx.x * blockDim.x + threadIdx.x;
    if (i < n4) {
        float4 v = x4[i];
        __half2 lo = __floats2half2_rn(v.x, v.y);
        __half2 hi = __floats2half2_rn(v.z, v.w);
        uint2 o;
        o.x = *reinterpret_cast<uint32_t*>(&lo);
        o.y = *reinterpret_cast<uint32_t*>(&hi);
        *reinterpret_cast<uint2*>(&g_xh[(long long)i * 4]) = o;
    }
}

// ---------------- W1 -> fp16 transposed [n][k] ----------------
__global__ void k_cvtw1t(const float* __restrict__ W1) {
    int i = blockIdx.x * blockDim.x + threadIdx.x;
    if (i < HIDDEN * IN_DIM) {
        int n = i / IN_DIM, k = i - n * IN_DIM;
        g_w1h[i] = __float2half_rn(W1[k * HIDDEN + n]);
    }
}

// ---------------- CSR build ----------------
__global__ void k_init_deg() {
    int n = blockIdx.x * blockDim.x + threadIdx.x;
    if (n < N_NODES) g_deg[n] = 1;
}

__global__ void k_hist(const void* __restrict__ ei, int E) {
    int e = blockIdx.x * blockDim.x + threadIdx.x;
    if (e < E) atomicAdd(&g_deg[load_edge(ei, E + e)], 1);
}

__global__ void k_s1() {
    __shared__ int sh[1024];
    int t = threadIdx.x;
    int i = blockIdx.x * 1024 + t;
    int v = (i < N_NODES) ? g_deg[i] : 0;
    sh[t] = v;
    __syncthreads();
    #pragma unroll
    for (int offs = 1; offs < 1024; offs <<= 1) {
        int add = (t >= offs) ? sh[t - offs] : 0;
        __syncthreads();
        sh[t] += add;
        __syncthreads();
    }
    if (i < N_NODES) {
        g_off[i]  = sh[t] - v;
        g_dinv[i] = rsqrtf((float)v);
    }
    if (t == 1023) g_bsum[blockIdx.x] = sh[1023];
}

__global__ void k_s2(int nblocks) {
    if (threadIdx.x == 0) {
        int acc = 0;
        for (int b = 0; b < nblocks; b++) {
            int v = g_bsum[b];
            g_bsum[b] = acc;
            acc += v;
        }
        g_off[N_NODES] = acc;
    }
}

__global__ void k_s3() {
    int i = blockIdx.x * 1024 + threadIdx.x;
    if (i < N_NODES) {
        int o = g_off[i] + g_bsum[blockIdx.x];
        g_off[i]    = o;
        g_cursor[i] = o;
    }
}

__global__ void k_fill(const void* __restrict__ ei, int E) {
    int idx = blockIdx.x * blockDim.x + threadIdx.x;
    int total = E + N_NODES;
    if (idx >= total) return;
    int s, d;
    if (idx < E) { s = load_edge(ei, idx); d = load_edge(ei, E + idx); }
    else         { s = d = idx - E; }
    int pos = atomicAdd(&g_cursor[d], 1);
    if (pos < MAX_ENTRIES) {
        g_csr_src[pos]  = s;
        g_csr_norm[pos] = g_dinv[s] * g_dinv[d];
    }
}

// ---------------- GEMM1: h1 = x @ W1, fp16 mma m16n8k16, 3-stage cp.async ------
#define NITER  63
#define STAGES 3
#define AW     (128 * 8)
#define BW     (128 * 8)

__device__ __forceinline__ void cpa16(uint32_t dst, const void* src, int sz) {
    asm volatile("cp.async.ca.shared.global [%0], [%1], 16, %2;"
                 :: "r"(dst), "l"(src), "r"(sz) : "memory");
}

__device__ __forceinline__ void gemm1_issue(
    int it, uint32_t (*Asw)[AW], uint32_t (*Bsw)[BW],
    int rowS, int cS, int gr, long long abase, long long bbase, int physChunk,
    const __half* xh, const __half* w1h)
{
    int st = it % STAGES;
    int k  = it * 16 + 8 * cS;
    int rem = IN_DIM - k;
    const uint32_t da = (uint32_t)__cvta_generic_to_shared(
                            &Asw[st][rowS * 8 + physChunk]);
    const uint32_t db = (uint32_t)__cvta_generic_to_shared(
                            &Bsw[st][rowS * 8 + physChunk]);
    int szA = (gr < N_NODES) ? min(max(rem, 0) * 2, 16) : 0;
    int szB = min(max(rem, 0) * 2, 16);
    int kc  = min(k, IN_DIM - 8);
    cpa16(da, xh  + abase + kc, szA);
    cpa16(db, w1h + bbase + kc, szB);
    asm volatile("cp.async.commit_group;" ::: "memory");
}

__global__ __launch_bounds__(256, 2) void k_gemm1() {
    __shared__ uint32_t Asw[STAGES][AW];
    __shared__ uint32_t Bsw[STAGES][BW];

    const int t    = threadIdx.x;
    const int lane = t & 31;
    const int wid  = t >> 5;
    const int wm   = wid & 3;
    const int wn   = wid >> 2;
    const int g    = lane >> 2;
    const int tig  = lane & 3;

    // grid swapped: x = n-block (2), y = m-block (391). Adjacent CTAs share
    // the same x rows -> second n-sweep hits L2.
    const int bm0 = blockIdx.y * 128;
    const int bn0 = blockIdx.x * 128;

    const int rowS = t >> 1;
    const int cS   = t & 1;
    const int gr   = bm0 + rowS;
    const long long abase = (long long)min(gr, N_NODES - 1) * IN_DIM;
    const int ngl  = bn0 + rowS;
    const long long bbase = (long long)ngl * IN_DIM;
    const int physChunk = ((4 * cS) ^ (rowS & 4));

    const __half* __restrict__ xh  = g_xh;
    const __half* __restrict__ w1h = g_w1h;

    float acc[2][8][4];
    #pragma unroll
    for (int mt = 0; mt < 2; mt++)
        #pragma unroll
        for (int nt = 0; nt < 8; nt++)
            #pragma unroll
            for (int r = 0; r < 4; r++) acc[mt][nt][r] = 0.f;

    gemm1_issue(0, Asw, Bsw, rowS, cS, gr, abase, bbase, physChunk, xh, w1h);
    gemm1_issue(1, Asw, Bsw, rowS, cS, gr, abase, bbase, physChunk, xh, w1h);

    const int wA  = tig ^ (g & 4);
    const int wA4 = wA ^ 4;

    for (int it = 0; it < NITER; it++) {
        if (it == NITER - 1) asm volatile("cp.async.wait_group 0;" ::: "memory");
        else                 asm volatile("cp.async.wait_group 1;" ::: "memory");
        __syncthreads();
        if (it + 2 < NITER)
            gemm1_issue(it + 2, Asw, Bsw, rowS, cS, gr, abase, bbase, physChunk, xh, w1h);

        const uint32_t* Ab = Asw[it % STAGES];
        const uint32_t* Bb = Bsw[it % STAGES];

        uint32_t af[2][4], bf[8][2];
        #pragma unroll
        for (int mt = 0; mt < 2; mt++) {
            int r0 = wm * 32 + mt * 16 + g;
            af[mt][0] = Ab[r0 * 8 + wA];
            af[mt][1] = Ab[(r0 + 8) * 8 + wA];
            af[mt][2] = Ab[r0 * 8 + wA4];
            af[mt][3] = Ab[(r0 + 8) * 8 + wA4];
        }
        #pragma unroll
        for (int nt = 0; nt < 8; nt++) {
            int nr = wn * 64 + nt * 8 + g;
            bf[nt][0] = Bb[nr * 8 + wA];
            bf[nt][1] = Bb[nr * 8 + wA4];
        }
        #pragma unroll
        for (int mt = 0; mt < 2; mt++)
            #pragma unroll
            for (int nt = 0; nt < 8; nt++) {
                asm volatile(
                    "mma.sync.aligned.m16n8k16.row.col.f32.f16.f16.f32 "
                    "{%0,%1,%2,%3}, {%4,%5,%6,%7}, {%8,%9}, {%0,%1,%2,%3};"
                    : "+f"(acc[mt][nt][0]), "+f"(acc[mt][nt][1]),
                      "+f"(acc[mt][nt][2]), "+f"(acc[mt][nt][3])
                    : "r"(af[mt][0]), "r"(af[mt][1]), "r"(af[mt][2]), "r"(af[mt][3]),
                      "r"(bf[nt][0]), "r"(bf[nt][1]));
            }
    }

    #pragma unroll
    for (int mt = 0; mt < 2; mt++) {
        #pragma unroll
        for (int nt = 0; nt < 8; nt++) {
            int col = bn0 + wn * 64 + nt * 8 + 2 * tig;
            int r0  = bm0 + wm * 32 + mt * 16 + g;
            if (r0 < N_NODES)
                *(__half2*)&g_h1h[(long long)r0 * HIDDEN + col] =
                    __floats2half2_rn(acc[mt][nt][0], acc[mt][nt][1]);
            int r1 = r0 + 8;
            if (r1 < N_NODES)
                *(__half2*)&g_h1h[(long long)r1 * HIDDEN + col] =
                    __floats2half2_rn(acc[mt][nt][2], acc[mt][nt][3]);
        }
    }
}

// ---------------- agg1 + bias + relu + GEMM2 fused: WARP PER NODE (MLP 8) -------
__device__ __forceinline__ void fma8(float* acc, uint4 v, float nm) {
    float2 f0 = __half22float2(*reinterpret_cast<__half2*>(&v.x));
    float2 f1 = __half22float2(*reinterpret_cast<__half2*>(&v.y));
    float2 f2 = __half22float2(*reinterpret_cast<__half2*>(&v.z));
    float2 f3 = __half22float2(*reinterpret_cast<__half2*>(&v.w));
    acc[0] = fmaf(f0.x, nm, acc[0]);
    acc[1] = fmaf(f0.y, nm, acc[1]);
    acc[2] = fmaf(f1.x, nm, acc[2]);
    acc[3] = fmaf(f1.y, nm, acc[3]);
    acc[4] = fmaf(f2.x, nm, acc[4]);
    acc[5] = fmaf(f2.y, nm, acc[5]);
    acc[6] = fmaf(f3.x, nm, acc[6]);
    acc[7] = fmaf(f3.y, nm, acc[7]);
}

__global__ __launch_bounds__(256) void k_agg1f(const float* __restrict__ b1,
                                               const float* __restrict__ W2) {
    const int warp = (blockIdx.x * blockDim.x + threadIdx.x) >> 5;
    const int lane = threadIdx.x & 31;
    if (warp >= N_NODES) return;
    const int n   = warp;
    const int beg = g_off[n];
    const int end = g_off[n + 1];

    const int*   __restrict__ csr_src  = g_csr_src;
    const float* __restrict__ csr_norm = g_csr_norm;
    const uint4* __restrict__ h1q      = (const uint4*)g_h1h;

    float acc[8];
    #pragma unroll
    for (int j = 0; j < 8; j++) acc[j] = 0.f;

    for (int base = beg; base < end; base += 32) {
        int i  = base + lane;
        int sv = 0; float nv = 0.f;
        if (i < end) { sv = csr_src[i]; nv = csr_norm[i]; }
        int cnt = min(32, end - base);
        int j = 0;
        for (; j + 8 <= cnt; j += 8) {           // 8 independent LDG.128 chains
            int   s[8]; float m[8]; uint4 v[8];
            #pragma unroll
            for (int q = 0; q < 8; q++) {
                s[q] = __shfl_sync(0xffffffffu, sv, j + q);
                m[q] = __shfl_sync(0xffffffffu, nv, j + q);
            }
            #pragma unroll
            for (int q = 0; q < 8; q++)
                v[q] = h1q[(long long)s[q] * 32 + lane];
            #pragma unroll
            for (int q = 0; q < 8; q++)
                fma8(acc, v[q], m[q]);
        }
        for (; j < cnt; j++) {
            int   s = __shfl_sync(0xffffffffu, sv, j);
            float m = __shfl_sync(0xffffffffu, nv, j);
            uint4 v = h1q[(long long)s * 32 + lane];
            fma8(acc, v, m);
        }
    }

    float4 bb0 = *(const float4*)&b1[lane * 8];
    float4 bb1 = *(const float4*)&b1[lane * 8 + 4];
    float h[8];
    h[0] = fmaxf(acc[0] + bb0.x, 0.f);
    h[1] = fmaxf(acc[1] + bb0.y, 0.f);
    h[2] = fmaxf(acc[2] + bb0.z, 0.f);
    h[3] = fmaxf(acc[3] + bb0.w, 0.f);
    h[4] = fmaxf(acc[4] + bb1.x, 0.f);
    h[5] = fmaxf(acc[5] + bb1.y, 0.f);
    h[6] = fmaxf(acc[6] + bb1.z, 0.f);
    h[7] = fmaxf(acc[7] + bb1.w, 0.f);

    // W2 row r occupies floats [2r, 2r+1]; lane owns rows 8*lane+j
    float p0 = 0.f, p1 = 0.f;
    #pragma unroll
    for (int j = 0; j < 8; j++) {
        float2 w = *(const float2*)&W2[(lane * 8 + j) * 2];
        p0 = fmaf(h[j], w.x, p0);
        p1 = fmaf(h[j], w.y, p1);
    }
    #pragma unroll
    for (int o = 16; o; o >>= 1) {
        p0 += __shfl_xor_sync(0xffffffffu, p0, o);
        p1 += __shfl_xor_sync(0xffffffffu, p1, o);
    }
    if (lane == 0) *(float2*)&g_h2[n * 2] = make_float2(p0, p1);
}

// ---------------- agg2 + bias -> out ----------------
__global__ __launch_bounds__(256) void k_agg2(const float* __restrict__ b2,
                                              float* __restrict__ out) {
    int warp = (blockIdx.x * blockDim.x + threadIdx.x) >> 5;
    int lane = threadIdx.x & 31;
    if (warp >= N_NODES) return;
    int beg = g_off[warp];
    int end = g_off[warp + 1];
    const int*   __restrict__ csr_src  = g_csr_src;
    const float* __restrict__ csr_norm = g_csr_norm;
    const float* __restrict__ h2       = g_h2;
    float a0 = 0.f, a1 = 0.f;
    for (int i = beg + lane; i < end; i += 32) {
        int s    = csr_src[i];
        float nm = csr_norm[i];
        float2 v = *(const float2*)&h2[s * 2];
        a0 = fmaf(v.x, nm, a0);
        a1 = fmaf(v.y, nm, a1);
    }
    #pragma unroll
    for (int o = 16; o; o >>= 1) {
        a0 += __shfl_xor_sync(0xffffffffu, a0, o);
        a1 += __shfl_xor_sync(0xffffffffu, a1, o);
    }
    if (lane == 0) {
        out[warp * 2 + 0] = a0 + b2[0];
        out[warp * 2 + 1] = a1 + b2[1];
    }
}

// ---------------- launch ----------------
extern "C" void kernel_launch(void* const* d_in, const int* in_sizes, int n_in,
                              void* d_out, int out_size) {
    const float* x   = nullptr;
    const float* W1  = nullptr;
    const float* b1  = nullptr;
    const float* W2  = nullptr;
    const float* b2  = nullptr;
    const void*  ei  = nullptr;
    int ei_elems = 0;
    for (int i = 0; i < n_in; i++) {
        switch (in_sizes[i]) {
            case 50000000: x  = (const float*)d_in[i]; break;
            case 256000:   W1 = (const float*)d_in[i]; break;
            case 256:      b1 = (const float*)d_in[i]; break;
            case 512:      W2 = (const float*)d_in[i]; break;
            case 2:        b2 = (const float*)d_in[i]; break;
            case 3200000:  ei = d_in[i]; ei_elems = in_sizes[i]; break;
            default: break;
        }
    }
    float* out = (float*)d_out;
    const int E = ei_elems / 2;
    const int SCAN_BLOCKS = (N_NODES + 1023) / 1024;
    const int N4 = N_NODES * IN_DIM / 4;

    // gemm1 stays the 4th launch (ncu capture slot).
    k_detect<<<1, 256>>>((const int*)ei, ei_elems);
    k_cvtx<<<(N4 + 255) / 256, 256>>>((const float4*)x, N4);
    k_cvtw1t<<<(HIDDEN * IN_DIM + 255) / 256, 256>>>(W1);
    dim3 g1(HIDDEN / 128, (N_NODES + 127) / 128);   // n fast, m slow: L2 x-reuse
    k_gemm1<<<g1, 256>>>();

    k_init_deg<<<(N_NODES + 255) / 256, 256>>>();
    k_hist<<<(E + 255) / 256, 256>>>(ei, E);
    k_s1<<<SCAN_BLOCKS, 1024>>>();
    k_s2<<<1, 32>>>(SCAN_BLOCKS);
    k_s3<<<SCAN_BLOCKS, 1024>>>();
    k_fill<<<(E + N_NODES + 255) / 256, 256>>>(ei, E);

    int warps_blocks = (N_NODES * 32 + 255) / 256;
    k_agg1f<<<warps_blocks, 256>>>(b1, W2);
    k_agg2<<<warps_blocks, 256>>>(b2, out);
}

// round 16
// speedup vs baseline: 1.0274x; 1.0274x over previous
#include <cuda_runtime.h>
#include <cuda_fp16.h>
#include <cuda_bf16.h>
#include <cstdint>

#define N_NODES 50000
#define IN_DIM  1000
#define HIDDEN  256
#define OUT_DIM 2
#define MAX_ENTRIES 1700000

// ---------------- scratch ----------------
__device__ __align__(16) __half g_xh[(long long)N_NODES * IN_DIM];  // x in fp16
__device__ __align__(16) __half g_w1h[HIDDEN * IN_DIM];             // W1^T fp16 [n][k]
__device__ __align__(16) __half g_h1h[N_NODES * HIDDEN];            // x@W1 fp16
__device__ __align__(16) float  g_h2[N_NODES * OUT_DIM];
__device__ int   g_deg[N_NODES];
__device__ int   g_off[N_NODES + 1];
__device__ int   g_cursor[N_NODES];
__device__ float g_dinv[N_NODES];
__device__ int   g_csr_src[MAX_ENTRIES];
__device__ float g_csr_norm[MAX_ENTRIES];
__device__ int   g_is64;
__device__ int   g_bsum[64];

// ---------------- dtype detect ----------------
__global__ void k_detect(const int* __restrict__ ei32, int n_words) {
    __shared__ int nz;
    if (threadIdx.x == 0) nz = 0;
    __syncthreads();
    for (int i = threadIdx.x; i < 32768; i += blockDim.x) {
        int w = 1 + 96 * i;
        if (w < n_words && ei32[w] != 0) nz = 1;
    }
    __syncthreads();
    if (threadIdx.x == 0) g_is64 = (nz == 0) ? 1 : 0;
}

__device__ __forceinline__ int load_edge(const void* ei, int pos) {
    int v;
    if (g_is64) v = (int)((const long long*)ei)[pos];
    else        v = ((const int*)ei)[pos];
    return min(max(v, 0), N_NODES - 1);
}

// ---------------- merged prep: hist | init_deg | cvtw1t | cvtx ------------------
#define NBX ((N_NODES * IN_DIM / 4 + 255) / 256)   // cvtx blocks (48829)
#define NBW ((HIDDEN * IN_DIM + 255) / 256)        // cvtw blocks (1000)
#define NBI ((N_NODES + 255) / 256)                // init blocks (196)

__global__ __launch_bounds__(256) void k_prep(const float4* __restrict__ x4, int n4,
                                              const float* __restrict__ W1,
                                              const void* __restrict__ ei, int E,
                                              int nb_hist) {
    const int b   = blockIdx.x;
    const int tid = threadIdx.x;
    if (b < nb_hist) {                       // hist (latency-bound; start first)
        int e = b * 256 + tid;
        if (e < E) atomicAdd(&g_deg[load_edge(ei, E + e)], 1);
    } else if (b < nb_hist + NBI) {          // init_deg -> deg=1 handled below!
        // NOTE: init must precede hist logically; instead deg starts at 0 and
        // the self-loop +1 is added in k_s1 (see there).
        // This branch left intentionally empty-cheap (kept for grid sizing).
    } else if (b < nb_hist + NBI + NBW) {    // W1 -> fp16 transposed
        int i = (b - nb_hist - NBI) * 256 + tid;
        if (i < HIDDEN * IN_DIM) {
            int n = i / IN_DIM, k = i - n * IN_DIM;
            g_w1h[i] = __float2half_rn(W1[k * HIDDEN + n]);
        }
    } else {                                 // x -> fp16
        int i = (b - nb_hist - NBI - NBW) * 256 + tid;
        if (i < n4) {
            float4 v = x4[i];
            __half2 lo = __floats2half2_rn(v.x, v.y);
            __half2 hi = __floats2half2_rn(v.z, v.w);
            uint2 o;
            o.x = *reinterpret_cast<uint32_t*>(&lo);
            o.y = *reinterpret_cast<uint32_t*>(&hi);
            *reinterpret_cast<uint2*>(&g_xh[(long long)i * 4]) = o;
        }
    }
}

// zero deg before prep (hist adds onto 0; self-loop +1 folded into k_s1)
__global__ void k_zero_deg() {
    int n = blockIdx.x * blockDim.x + threadIdx.x;
    if (n < N_NODES) g_deg[n] = 0;
}

// ---------------- scan stage 1: local scan + dinv (deg+1 for self loop) ---------
__global__ void k_s1() {
    __shared__ int sh[1024];
    int t = threadIdx.x;
    int i = blockIdx.x * 1024 + t;
    int v = (i < N_NODES) ? (g_deg[i] + 1) : 0;   // +1 = self loop
    sh[t] = v;
    __syncthreads();
    #pragma unroll
    for (int offs = 1; offs < 1024; offs <<= 1) {
        int add = (t >= offs) ? sh[t - offs] : 0;
        __syncthreads();
        sh[t] += add;
        __syncthreads();
    }
    if (i < N_NODES) {
        g_off[i]  = sh[t] - v;
        g_dinv[i] = rsqrtf((float)v);
    }
    if (t == 1023) g_bsum[blockIdx.x] = sh[1023];
}

// ---------------- scan stage 2+3 fused: per-block serial bsum prefix ------------
__global__ void k_s3(int nblocks) {
    __shared__ int carry;
    if (threadIdx.x == 0) {
        int c = 0;
        for (int b2 = 0; b2 < blockIdx.x; b2++) c += g_bsum[b2];
        carry = c;
        if (blockIdx.x == nblocks - 1) g_off[N_NODES] = c + g_bsum[blockIdx.x];
    }
    __syncthreads();
    int i = blockIdx.x * 1024 + threadIdx.x;
    if (i < N_NODES) {
        int o = g_off[i] + carry;
        g_off[i]    = o;
        g_cursor[i] = o;
    }
}

// ---------------- GEMM1 (fp16 mma, 3-stage cp.async) + fill merged ---------------
#define NITER  63
#define STAGES 3
#define AW     (128 * 8)
#define BW     (128 * 8)
#define GEMM_BLOCKS 782      // 391 m-blocks x 2 n-blocks, m-fast

__device__ __forceinline__ void cpa16(uint32_t dst, const void* src, int sz) {
    asm volatile("cp.async.ca.shared.global [%0], [%1], 16, %2;"
                 :: "r"(dst), "l"(src), "r"(sz) : "memory");
}

__device__ __forceinline__ void gemm1_issue(
    int it, uint32_t (*Asw)[AW], uint32_t (*Bsw)[BW],
    int rowS, int cS, int gr, long long abase, long long bbase, int physChunk,
    const __half* xh, const __half* w1h)
{
    int st = it % STAGES;
    int k  = it * 16 + 8 * cS;
    int rem = IN_DIM - k;
    const uint32_t da = (uint32_t)__cvta_generic_to_shared(
                            &Asw[st][rowS * 8 + physChunk]);
    const uint32_t db = (uint32_t)__cvta_generic_to_shared(
                            &Bsw[st][rowS * 8 + physChunk]);
    int szA = (gr < N_NODES) ? min(max(rem, 0) * 2, 16) : 0;
    int szB = min(max(rem, 0) * 2, 16);
    int kc  = min(k, IN_DIM - 8);
    cpa16(da, xh  + abase + kc, szA);
    cpa16(db, w1h + bbase + kc, szB);
    asm volatile("cp.async.commit_group;" ::: "memory");
}

__global__ __launch_bounds__(256, 2) void k_gemm1f(const void* __restrict__ ei, int E) {
    __shared__ uint32_t Asw[STAGES][AW];
    __shared__ uint32_t Bsw[STAGES][BW];

    const int t = threadIdx.x;

    if (blockIdx.x >= GEMM_BLOCKS) {
        // -------- fill branch (rides gemm's idle issue slots) --------
        int idx = (blockIdx.x - GEMM_BLOCKS) * 256 + t;
        int total = E + N_NODES;
        if (idx < total) {
            int s, d;
            if (idx < E) { s = load_edge(ei, idx); d = load_edge(ei, E + idx); }
            else         { s = d = idx - E; }
            int pos = atomicAdd(&g_cursor[d], 1);
            if (pos < MAX_ENTRIES) {
                g_csr_src[pos]  = s;
                g_csr_norm[pos] = g_dinv[s] * g_dinv[d];
            }
        }
        return;
    }

    // -------- gemm branch --------
    const int lane = t & 31;
    const int wid  = t >> 5;
    const int wm   = wid & 3;
    const int wn   = wid >> 2;
    const int g    = lane >> 2;
    const int tig  = lane & 3;

    // m-fast linear mapping (equivalent to R14's grid (391, 2))
    const int mb  = (blockIdx.x < 391) ? blockIdx.x : blockIdx.x - 391;
    const int nb  = (blockIdx.x < 391) ? 0 : 1;
    const int bm0 = mb * 128;
    const int bn0 = nb * 128;

    const int rowS = t >> 1;
    const int cS   = t & 1;
    const int gr   = bm0 + rowS;
    const long long abase = (long long)min(gr, N_NODES - 1) * IN_DIM;
    const int ngl  = bn0 + rowS;
    const long long bbase = (long long)ngl * IN_DIM;
    const int physChunk = ((4 * cS) ^ (rowS & 4));

    const __half* __restrict__ xh  = g_xh;
    const __half* __restrict__ w1h = g_w1h;

    float acc[2][8][4];
    #pragma unroll
    for (int mt = 0; mt < 2; mt++)
        #pragma unroll
        for (int nt = 0; nt < 8; nt++)
            #pragma unroll
            for (int r = 0; r < 4; r++) acc[mt][nt][r] = 0.f;

    gemm1_issue(0, Asw, Bsw, rowS, cS, gr, abase, bbase, physChunk, xh, w1h);
    gemm1_issue(1, Asw, Bsw, rowS, cS, gr, abase, bbase, physChunk, xh, w1h);

    const int wA  = tig ^ (g & 4);
    const int wA4 = wA ^ 4;

    for (int it = 0; it < NITER; it++) {
        if (it == NITER - 1) asm volatile("cp.async.wait_group 0;" ::: "memory");
        else                 asm volatile("cp.async.wait_group 1;" ::: "memory");
        __syncthreads();
        if (it + 2 < NITER)
            gemm1_issue(it + 2, Asw, Bsw, rowS, cS, gr, abase, bbase, physChunk, xh, w1h);

        const uint32_t* Ab = Asw[it % STAGES];
        const uint32_t* Bb = Bsw[it % STAGES];

        uint32_t af[2][4], bf[8][2];
        #pragma unroll
        for (int mt = 0; mt < 2; mt++) {
            int r0 = wm * 32 + mt * 16 + g;
            af[mt][0] = Ab[r0 * 8 + wA];
            af[mt][1] = Ab[(r0 + 8) * 8 + wA];
            af[mt][2] = Ab[r0 * 8 + wA4];
            af[mt][3] = Ab[(r0 + 8) * 8 + wA4];
        }
        #pragma unroll
        for (int nt = 0; nt < 8; nt++) {
            int nr = wn * 64 + nt * 8 + g;
            bf[nt][0] = Bb[nr * 8 + wA];
            bf[nt][1] = Bb[nr * 8 + wA4];
        }
        #pragma unroll
        for (int mt = 0; mt < 2; mt++)
            #pragma unroll
            for (int nt = 0; nt < 8; nt++) {
                asm volatile(
                    "mma.sync.aligned.m16n8k16.row.col.f32.f16.f16.f32 "
                    "{%0,%1,%2,%3}, {%4,%5,%6,%7}, {%8,%9}, {%0,%1,%2,%3};"
                    : "+f"(acc[mt][nt][0]), "+f"(acc[mt][nt][1]),
                      "+f"(acc[mt][nt][2]), "+f"(acc[mt][nt][3])
                    : "r"(af[mt][0]), "r"(af[mt][1]), "r"(af[mt][2]), "r"(af[mt][3]),
                      "r"(bf[nt][0]), "r"(bf[nt][1]));
            }
    }

    #pragma unroll
    for (int mt = 0; mt < 2; mt++) {
        #pragma unroll
        for (int nt = 0; nt < 8; nt++) {
            int col = bn0 + wn * 64 + nt * 8 + 2 * tig;
            int r0  = bm0 + wm * 32 + mt * 16 + g;
            if (r0 < N_NODES)
                *(__half2*)&g_h1h[(long long)r0 * HIDDEN + col] =
                    __floats2half2_rn(acc[mt][nt][0], acc[mt][nt][1]);
            int r1 = r0 + 8;
            if (r1 < N_NODES)
                *(__half2*)&g_h1h[(long long)r1 * HIDDEN + col] =
                    __floats2half2_rn(acc[mt][nt][2], acc[mt][nt][3]);
        }
    }
}

// ---------------- agg1 + bias + relu + GEMM2 fused: WARP PER NODE (R14) ---------
__device__ __forceinline__ void fma8(float* acc, uint4 v, float nm) {
    float2 f0 = __half22float2(*reinterpret_cast<__half2*>(&v.x));
    float2 f1 = __half22float2(*reinterpret_cast<__half2*>(&v.y));
    float2 f2 = __half22float2(*reinterpret_cast<__half2*>(&v.z));
    float2 f3 = __half22float2(*reinterpret_cast<__half2*>(&v.w));
    acc[0] = fmaf(f0.x, nm, acc[0]);
    acc[1] = fmaf(f0.y, nm, acc[1]);
    acc[2] = fmaf(f1.x, nm, acc[2]);
    acc[3] = fmaf(f1.y, nm, acc[3]);
    acc[4] = fmaf(f2.x, nm, acc[4]);
    acc[5] = fmaf(f2.y, nm, acc[5]);
    acc[6] = fmaf(f3.x, nm, acc[6]);
    acc[7] = fmaf(f3.y, nm, acc[7]);
}

__global__ __launch_bounds__(256) void k_agg1f(const float* __restrict__ b1,
                                               const float* __restrict__ W2) {
    const int warp = (blockIdx.x * blockDim.x + threadIdx.x) >> 5;
    const int lane = threadIdx.x & 31;
    if (warp >= N_NODES) return;
    const int n   = warp;
    const int beg = g_off[n];
    const int end = g_off[n + 1];

    const int*   __restrict__ csr_src  = g_csr_src;
    const float* __restrict__ csr_norm = g_csr_norm;
    const uint4* __restrict__ h1q      = (const uint4*)g_h1h;

    float acc[8];
    #pragma unroll
    for (int j = 0; j < 8; j++) acc[j] = 0.f;

    for (int base = beg; base < end; base += 32) {
        int i  = base + lane;
        int sv = 0; float nv = 0.f;
        if (i < end) { sv = csr_src[i]; nv = csr_norm[i]; }
        int cnt = min(32, end - base);
        int j = 0;
        for (; j + 4 <= cnt; j += 4) {
            int   s0 = __shfl_sync(0xffffffffu, sv, j);
            int   s1 = __shfl_sync(0xffffffffu, sv, j + 1);
            int   s2 = __shfl_sync(0xffffffffu, sv, j + 2);
            int   s3 = __shfl_sync(0xffffffffu, sv, j + 3);
            float n0 = __shfl_sync(0xffffffffu, nv, j);
            float n1 = __shfl_sync(0xffffffffu, nv, j + 1);
            float n2 = __shfl_sync(0xffffffffu, nv, j + 2);
            float n3 = __shfl_sync(0xffffffffu, nv, j + 3);
            uint4 v0 = h1q[(long long)s0 * 32 + lane];
            uint4 v1 = h1q[(long long)s1 * 32 + lane];
            uint4 v2 = h1q[(long long)s2 * 32 + lane];
            uint4 v3 = h1q[(long long)s3 * 32 + lane];
            fma8(acc, v0, n0);
            fma8(acc, v1, n1);
            fma8(acc, v2, n2);
            fma8(acc, v3, n3);
        }
        for (; j < cnt; j++) {
            int   s = __shfl_sync(0xffffffffu, sv, j);
            float m = __shfl_sync(0xffffffffu, nv, j);
            uint4 v = h1q[(long long)s * 32 + lane];
            fma8(acc, v, m);
        }
    }

    float4 bb0 = *(const float4*)&b1[lane * 8];
    float4 bb1 = *(const float4*)&b1[lane * 8 + 4];
    float h[8];
    h[0] = fmaxf(acc[0] + bb0.x, 0.f);
    h[1] = fmaxf(acc[1] + bb0.y, 0.f);
    h[2] = fmaxf(acc[2] + bb0.z, 0.f);
    h[3] = fmaxf(acc[3] + bb0.w, 0.f);
    h[4] = fmaxf(acc[4] + bb1.x, 0.f);
    h[5] = fmaxf(acc[5] + bb1.y, 0.f);
    h[6] = fmaxf(acc[6] + bb1.z, 0.f);
    h[7] = fmaxf(acc[7] + bb1.w, 0.f);

    // W2 row r occupies floats [2r, 2r+1]; lane owns rows 8*lane+j
    float p0 = 0.f, p1 = 0.f;
    #pragma unroll
    for (int j = 0; j < 8; j++) {
        float2 w = *(const float2*)&W2[(lane * 8 + j) * 2];
        p0 = fmaf(h[j], w.x, p0);
        p1 = fmaf(h[j], w.y, p1);
    }
    #pragma unroll
    for (int o = 16; o; o >>= 1) {
        p0 += __shfl_xor_sync(0xffffffffu, p0, o);
        p1 += __shfl_xor_sync(0xffffffffu, p1, o);
    }
    if (lane == 0) *(float2*)&g_h2[n * 2] = make_float2(p0, p1);
}

// ---------------- agg2 + bias -> out ----------------
__global__ __launch_bounds__(256) void k_agg2(const float* __restrict__ b2,
                                              float* __restrict__ out) {
    int warp = (blockIdx.x * blockDim.x + threadIdx.x) >> 5;
    int lane = threadIdx.x & 31;
    if (warp >= N_NODES) return;
    int beg = g_off[warp];
    int end = g_off[warp + 1];
    const int*   __restrict__ csr_src  = g_csr_src;
    const float* __restrict__ csr_norm = g_csr_norm;
    const float* __restrict__ h2       = g_h2;
    float a0 = 0.f, a1 = 0.f;
    for (int i = beg + lane; i < end; i += 32) {
        int s    = csr_src[i];
        float nm = csr_norm[i];
        float2 v = *(const float2*)&h2[s * 2];
        a0 = fmaf(v.x, nm, a0);
        a1 = fmaf(v.y, nm, a1);
    }
    #pragma unroll
    for (int o = 16; o; o >>= 1) {
        a0 += __shfl_xor_sync(0xffffffffu, a0, o);
        a1 += __shfl_xor_sync(0xffffffffu, a1, o);
    }
    if (lane == 0) {
        out[warp * 2 + 0] = a0 + b2[0];
        out[warp * 2 + 1] = a1 + b2[1];
    }
}

// ---------------- launch ----------------
extern "C" void kernel_launch(void* const* d_in, const int* in_sizes, int n_in,
                              void* d_out, int out_size) {
    const float* x   = nullptr;
    const float* W1  = nullptr;
    const float* b1  = nullptr;
    const float* W2  = nullptr;
    const float* b2  = nullptr;
    const void*  ei  = nullptr;
    int ei_elems = 0;
    for (int i = 0; i < n_in; i++) {
        switch (in_sizes[i]) {
            case 50000000: x  = (const float*)d_in[i]; break;
            case 256000:   W1 = (const float*)d_in[i]; break;
            case 256:      b1 = (const float*)d_in[i]; break;
            case 512:      W2 = (const float*)d_in[i]; break;
            case 2:        b2 = (const float*)d_in[i]; break;
            case 3200000:  ei = d_in[i]; ei_elems = in_sizes[i]; break;
            default: break;
        }
    }
    float* out = (float*)d_out;
    const int E = ei_elems / 2;
    const int SCAN_BLOCKS = (N_NODES + 1023) / 1024;
    const int N4 = N_NODES * IN_DIM / 4;
    const int NB_HIST = (E + 255) / 256;

    // 1. dtype detect (hist in k_prep depends on it) + zero deg
    k_detect<<<1, 256>>>((const int*)ei, ei_elems);
    k_zero_deg<<<(N_NODES + 255) / 256, 256>>>();
    // 2. merged prep: hist | (spare) | cvtw1t | cvtx
    int prep_blocks = NB_HIST + NBI + NBW + NBX;
    k_prep<<<prep_blocks, 256>>>((const float4*)x, N4, W1, ei, E, NB_HIST);
    // 3-4. scan
    k_s1<<<SCAN_BLOCKS, 1024>>>();
    k_s3<<<SCAN_BLOCKS, 1024>>>(SCAN_BLOCKS);
    // 5. gemm1 + fill merged
    int fill_blocks = (E + N_NODES + 255) / 256;
    k_gemm1f<<<GEMM_BLOCKS + fill_blocks, 256>>>(ei, E);
    // 6-7. layer-1 epilogue + layer 2
    int warps_blocks = (N_NODES * 32 + 255) / 256;
    k_agg1f<<<warps_blocks, 256>>>(b1, W2);
    k_agg2<<<warps_blocks, 256>>>(b2, out);
}

// round 17
// speedup vs baseline: 1.0639x; 1.0355x over previous
#include <cuda_runtime.h>
#include <cuda_fp16.h>
#include <cuda_bf16.h>
#include <cstdint>

#define N_NODES 50000
#define IN_DIM  1000
#define HIDDEN  256
#define OUT_DIM 2
#define MAX_ENTRIES 1700000

// ---------------- scratch ----------------
__device__ __align__(16) __half g_xh[(long long)N_NODES * IN_DIM];  // x in fp16
__device__ __align__(16) __half g_w1h[HIDDEN * IN_DIM];             // W1^T fp16 [n][k]
__device__ __align__(16) __half g_h1h[N_NODES * HIDDEN];            // x@W1 fp16
__device__ __align__(16) float  g_h2[N_NODES * OUT_DIM];
__device__ int   g_deg[N_NODES];
__device__ int   g_off[N_NODES + 1];
__device__ int   g_cursor[N_NODES];
__device__ float g_dinv[N_NODES];
__device__ int   g_csr_src[MAX_ENTRIES];
__device__ float g_csr_norm[MAX_ENTRIES];
__device__ int   g_is64;
__device__ int   g_bsum[64];

// ---------------- dtype detect ----------------
__global__ void k_detect(const int* __restrict__ ei32, int n_words) {
    __shared__ int nz;
    if (threadIdx.x == 0) nz = 0;
    __syncthreads();
    for (int i = threadIdx.x; i < 32768; i += blockDim.x) {
        int w = 1 + 96 * i;
        if (w < n_words && ei32[w] != 0) nz = 1;
    }
    __syncthreads();
    if (threadIdx.x == 0) g_is64 = (nz == 0) ? 1 : 0;
}

__device__ __forceinline__ int load_edge(const void* ei, int pos) {
    int v;
    if (g_is64) v = (int)((const long long*)ei)[pos];
    else        v = ((const int*)ei)[pos];
    return min(max(v, 0), N_NODES - 1);
}

// ---------------- merged prep: hist | (spare) | cvtw1t | cvtx -------------------
#define NBX ((N_NODES * IN_DIM / 4 + 255) / 256)
#define NBW ((HIDDEN * IN_DIM + 255) / 256)
#define NBI ((N_NODES + 255) / 256)

__global__ __launch_bounds__(256) void k_prep(const float4* __restrict__ x4, int n4,
                                              const float* __restrict__ W1,
                                              const void* __restrict__ ei, int E,
                                              int nb_hist) {
    const int b   = blockIdx.x;
    const int tid = threadIdx.x;
    if (b < nb_hist) {
        int e = b * 256 + tid;
        if (e < E) atomicAdd(&g_deg[load_edge(ei, E + e)], 1);
    } else if (b < nb_hist + NBI) {
        // spare (self-loop +1 folded into k_s1)
    } else if (b < nb_hist + NBI + NBW) {
        int i = (b - nb_hist - NBI) * 256 + tid;
        if (i < HIDDEN * IN_DIM) {
            int n = i / IN_DIM, k = i - n * IN_DIM;
            g_w1h[i] = __float2half_rn(W1[k * HIDDEN + n]);
        }
    } else {
        int i = (b - nb_hist - NBI - NBW) * 256 + tid;
        if (i < n4) {
            float4 v = x4[i];
            __half2 lo = __floats2half2_rn(v.x, v.y);
            __half2 hi = __floats2half2_rn(v.z, v.w);
            uint2 o;
            o.x = *reinterpret_cast<uint32_t*>(&lo);
            o.y = *reinterpret_cast<uint32_t*>(&hi);
            *reinterpret_cast<uint2*>(&g_xh[(long long)i * 4]) = o;
        }
    }
}

__global__ void k_zero_deg() {
    int n = blockIdx.x * blockDim.x + threadIdx.x;
    if (n < N_NODES) g_deg[n] = 0;
}

// ---------------- scan stage 1 ----------------
__global__ void k_s1() {
    __shared__ int sh[1024];
    int t = threadIdx.x;
    int i = blockIdx.x * 1024 + t;
    int v = (i < N_NODES) ? (g_deg[i] + 1) : 0;   // +1 = self loop
    sh[t] = v;
    __syncthreads();
    #pragma unroll
    for (int offs = 1; offs < 1024; offs <<= 1) {
        int add = (t >= offs) ? sh[t - offs] : 0;
        __syncthreads();
        sh[t] += add;
        __syncthreads();
    }
    if (i < N_NODES) {
        g_off[i]  = sh[t] - v;
        g_dinv[i] = rsqrtf((float)v);
    }
    if (t == 1023) g_bsum[blockIdx.x] = sh[1023];
}

// ---------------- scan stage 2+3 fused ----------------
__global__ void k_s3(int nblocks) {
    __shared__ int carry;
    if (threadIdx.x == 0) {
        int c = 0;
        for (int b2 = 0; b2 < blockIdx.x; b2++) c += g_bsum[b2];
        carry = c;
        if (blockIdx.x == nblocks - 1) g_off[N_NODES] = c + g_bsum[blockIdx.x];
    }
    __syncthreads();
    int i = blockIdx.x * 1024 + threadIdx.x;
    if (i < N_NODES) {
        int o = g_off[i] + carry;
        g_off[i]    = o;
        g_cursor[i] = o;
    }
}

// ---------------- GEMM1 (fp16 mma + LDSM fragment loads) + fill merged ----------
#define NITER  63
#define STAGES 3
#define AW     (128 * 8)
#define BW     (128 * 8)
#define GEMM_BLOCKS 782

__device__ __forceinline__ void cpa16(uint32_t dst, const void* src, int sz) {
    asm volatile("cp.async.ca.shared.global [%0], [%1], 16, %2;"
                 :: "r"(dst), "l"(src), "r"(sz) : "memory");
}

__device__ __forceinline__ void gemm1_issue(
    int it, uint32_t (*Asw)[AW], uint32_t (*Bsw)[BW],
    int rowS, int cS, int gr, long long abase, long long bbase, int physChunk,
    const __half* xh, const __half* w1h)
{
    int st = it % STAGES;
    int k  = it * 16 + 8 * cS;
    int rem = IN_DIM - k;
    const uint32_t da = (uint32_t)__cvta_generic_to_shared(
                            &Asw[st][rowS * 8 + physChunk]);
    const uint32_t db = (uint32_t)__cvta_generic_to_shared(
                            &Bsw[st][rowS * 8 + physChunk]);
    int szA = (gr < N_NODES) ? min(max(rem, 0) * 2, 16) : 0;
    int szB = min(max(rem, 0) * 2, 16);
    int kc  = min(k, IN_DIM - 8);
    cpa16(da, xh  + abase + kc, szA);
    cpa16(db, w1h + bbase + kc, szB);
    asm volatile("cp.async.commit_group;" ::: "memory");
}

__device__ __forceinline__ void ldsm4(uint32_t* r, uint32_t addr) {
    asm volatile("ldmatrix.sync.aligned.m8n8.x4.shared.b16 {%0,%1,%2,%3}, [%4];"
                 : "=r"(r[0]), "=r"(r[1]), "=r"(r[2]), "=r"(r[3]) : "r"(addr));
}

__global__ __launch_bounds__(256, 2) void k_gemm1f(const void* __restrict__ ei, int E) {
    __shared__ uint32_t Asw[STAGES][AW];
    __shared__ uint32_t Bsw[STAGES][BW];

    const int t = threadIdx.x;

    if (blockIdx.x >= GEMM_BLOCKS) {
        // -------- fill branch --------
        int idx = (blockIdx.x - GEMM_BLOCKS) * 256 + t;
        int total = E + N_NODES;
        if (idx < total) {
            int s, d;
            if (idx < E) { s = load_edge(ei, idx); d = load_edge(ei, E + idx); }
            else         { s = d = idx - E; }
            int pos = atomicAdd(&g_cursor[d], 1);
            if (pos < MAX_ENTRIES) {
                g_csr_src[pos]  = s;
                g_csr_norm[pos] = g_dinv[s] * g_dinv[d];
            }
        }
        return;
    }

    // -------- gemm branch --------
    const int lane = t & 31;
    const int wid  = t >> 5;
    const int wm   = wid & 3;
    const int wn   = wid >> 2;
    const int g    = lane >> 2;
    const int tig  = lane & 3;

    const int mb  = (blockIdx.x < 391) ? blockIdx.x : blockIdx.x - 391;
    const int nb  = (blockIdx.x < 391) ? 0 : 1;
    const int bm0 = mb * 128;
    const int bn0 = nb * 128;

    const int rowS = t >> 1;
    const int cS   = t & 1;
    const int gr   = bm0 + rowS;
    const long long abase = (long long)min(gr, N_NODES - 1) * IN_DIM;
    const int ngl  = bn0 + rowS;
    const long long bbase = (long long)ngl * IN_DIM;
    const int physChunk = ((4 * cS) ^ (rowS & 4));

    const __half* __restrict__ xh  = g_xh;
    const __half* __restrict__ w1h = g_w1h;

    // ldmatrix per-lane addresses (loop-invariant word offsets within a stage)
    // A x4: lanes 0-7/8-15 -> rows R+l15 chunk0; 16-23/24-31 -> chunk1.
    //   row = wm*32 + (lane&15); logical chunk = lane>>4; phys = ch ^ ((row>>2)&1)
    // B x4 (non-trans, n-major storage): lanes 0-7: n+l7 ch0; 8-15: n+l7 ch1;
    //   16-23: n+8+l7 ch0; 24-31: n+8+l7 ch1.
    const int l15 = lane & 15;
    const int l7  = lane & 7;
    const uint32_t aoff =
        (uint32_t)(((wm * 32 + l15) * 8 +
                    (((lane >> 4) ^ ((l15 >> 2) & 1)) << 2)) * 4);
    const uint32_t boff =
        (uint32_t)(((wn * 64 + l7 + ((lane >> 4) << 3)) * 8 +
                    ((((lane >> 3) & 1) ^ ((l7 >> 2) & 1)) << 2)) * 4);
    const uint32_t aBase = (uint32_t)__cvta_generic_to_shared(&Asw[0][0]) + aoff;
    const uint32_t bBase = (uint32_t)__cvta_generic_to_shared(&Bsw[0][0]) + boff;

    float acc[2][8][4];
    #pragma unroll
    for (int mt = 0; mt < 2; mt++)
        #pragma unroll
        for (int nt = 0; nt < 8; nt++)
            #pragma unroll
            for (int r = 0; r < 4; r++) acc[mt][nt][r] = 0.f;

    gemm1_issue(0, Asw, Bsw, rowS, cS, gr, abase, bbase, physChunk, xh, w1h);
    gemm1_issue(1, Asw, Bsw, rowS, cS, gr, abase, bbase, physChunk, xh, w1h);

    for (int it = 0; it < NITER; it++) {
        if (it == NITER - 1) asm volatile("cp.async.wait_group 0;" ::: "memory");
        else                 asm volatile("cp.async.wait_group 1;" ::: "memory");
        __syncthreads();
        if (it + 2 < NITER)
            gemm1_issue(it + 2, Asw, Bsw, rowS, cS, gr, abase, bbase, physChunk, xh, w1h);

        const int st = it % STAGES;
        const uint32_t aAddr = aBase + st * (AW * 4);
        const uint32_t bAddr = bBase + st * (BW * 4);

        uint32_t af[2][4], bf[8][2];
        #pragma unroll
        for (int mt = 0; mt < 2; mt++)
            ldsm4(af[mt], aAddr + mt * 512);       // 16 rows * 32B
        #pragma unroll
        for (int p = 0; p < 4; p++) {
            uint32_t r[4];
            ldsm4(r, bAddr + p * 512);             // n16 pair: (b0,b1) x 2 tiles
            bf[2 * p][0]     = r[0];
            bf[2 * p][1]     = r[1];
            bf[2 * p + 1][0] = r[2];
            bf[2 * p + 1][1] = r[3];
        }

        #pragma unroll
        for (int mt = 0; mt < 2; mt++)
            #pragma unroll
            for (int nt = 0; nt < 8; nt++) {
                asm volatile(
                    "mma.sync.aligned.m16n8k16.row.col.f32.f16.f16.f32 "
                    "{%0,%1,%2,%3}, {%4,%5,%6,%7}, {%8,%9}, {%0,%1,%2,%3};"
                    : "+f"(acc[mt][nt][0]), "+f"(acc[mt][nt][1]),
                      "+f"(acc[mt][nt][2]), "+f"(acc[mt][nt][3])
                    : "r"(af[mt][0]), "r"(af[mt][1]), "r"(af[mt][2]), "r"(af[mt][3]),
                      "r"(bf[nt][0]), "r"(bf[nt][1]));
            }
    }

    #pragma unroll
    for (int mt = 0; mt < 2; mt++) {
        #pragma unroll
        for (int nt = 0; nt < 8; nt++) {
            int col = bn0 + wn * 64 + nt * 8 + 2 * tig;
            int r0  = bm0 + wm * 32 + mt * 16 + g;
            if (r0 < N_NODES)
                *(__half2*)&g_h1h[(long long)r0 * HIDDEN + col] =
                    __floats2half2_rn(acc[mt][nt][0], acc[mt][nt][1]);
            int r1 = r0 + 8;
            if (r1 < N_NODES)
                *(__half2*)&g_h1h[(long long)r1 * HIDDEN + col] =
                    __floats2half2_rn(acc[mt][nt][2], acc[mt][nt][3]);
        }
    }
}

// ---------------- agg1 + bias + relu + GEMM2 fused: WARP PER NODE ---------------
__device__ __forceinline__ void fma8(float* acc, uint4 v, float nm) {
    float2 f0 = __half22float2(*reinterpret_cast<__half2*>(&v.x));
    float2 f1 = __half22float2(*reinterpret_cast<__half2*>(&v.y));
    float2 f2 = __half22float2(*reinterpret_cast<__half2*>(&v.z));
    float2 f3 = __half22float2(*reinterpret_cast<__half2*>(&v.w));
    acc[0] = fmaf(f0.x, nm, acc[0]);
    acc[1] = fmaf(f0.y, nm, acc[1]);
    acc[2] = fmaf(f1.x, nm, acc[2]);
    acc[3] = fmaf(f1.y, nm, acc[3]);
    acc[4] = fmaf(f2.x, nm, acc[4]);
    acc[5] = fmaf(f2.y, nm, acc[5]);
    acc[6] = fmaf(f3.x, nm, acc[6]);
    acc[7] = fmaf(f3.y, nm, acc[7]);
}

__global__ __launch_bounds__(256) void k_agg1f(const float* __restrict__ b1,
                                               const float* __restrict__ W2) {
    const int warp = (blockIdx.x * blockDim.x + threadIdx.x) >> 5;
    const int lane = threadIdx.x & 31;
    if (warp >= N_NODES) return;
    const int n   = warp;
    const int beg = g_off[n];
    const int end = g_off[n + 1];

    const int*   __restrict__ csr_src  = g_csr_src;
    const float* __restrict__ csr_norm = g_csr_norm;
    const uint4* __restrict__ h1q      = (const uint4*)g_h1h;

    float acc[8];
    #pragma unroll
    for (int j = 0; j < 8; j++) acc[j] = 0.f;

    for (int base = beg; base < end; base += 32) {
        int i  = base + lane;
        int sv = 0; float nv = 0.f;
        if (i < end) { sv = csr_src[i]; nv = csr_norm[i]; }
        int cnt = min(32, end - base);
        int j = 0;
        for (; j + 4 <= cnt; j += 4) {
            int   s0 = __shfl_sync(0xffffffffu, sv, j);
            int   s1 = __shfl_sync(0xffffffffu, sv, j + 1);
            int   s2 = __shfl_sync(0xffffffffu, sv, j + 2);
            int   s3 = __shfl_sync(0xffffffffu, sv, j + 3);
            float n0 = __shfl_sync(0xffffffffu, nv, j);
            float n1 = __shfl_sync(0xffffffffu, nv, j + 1);
            float n2 = __shfl_sync(0xffffffffu, nv, j + 2);
            float n3 = __shfl_sync(0xffffffffu, nv, j + 3);
            uint4 v0 = h1q[(long long)s0 * 32 + lane];
            uint4 v1 = h1q[(long long)s1 * 32 + lane];
            uint4 v2 = h1q[(long long)s2 * 32 + lane];
            uint4 v3 = h1q[(long long)s3 * 32 + lane];
            fma8(acc, v0, n0);
            fma8(acc, v1, n1);
            fma8(acc, v2, n2);
            fma8(acc, v3, n3);
        }
        for (; j < cnt; j++) {
            int   s = __shfl_sync(0xffffffffu, sv, j);
            float m = __shfl_sync(0xffffffffu, nv, j);
            uint4 v = h1q[(long long)s * 32 + lane];
            fma8(acc, v, m);
        }
    }

    float4 bb0 = *(const float4*)&b1[lane * 8];
    float4 bb1 = *(const float4*)&b1[lane * 8 + 4];
    float h[8];
    h[0] = fmaxf(acc[0] + bb0.x, 0.f);
    h[1] = fmaxf(acc[1] + bb0.y, 0.f);
    h[2] = fmaxf(acc[2] + bb0.z, 0.f);
    h[3] = fmaxf(acc[3] + bb0.w, 0.f);
    h[4] = fmaxf(acc[4] + bb1.x, 0.f);
    h[5] = fmaxf(acc[5] + bb1.y, 0.f);
    h[6] = fmaxf(acc[6] + bb1.z, 0.f);
    h[7] = fmaxf(acc[7] + bb1.w, 0.f);

    float p0 = 0.f, p1 = 0.f;
    #pragma unroll
    for (int j = 0; j < 8; j++) {
        float2 w = *(const float2*)&W2[(lane * 8 + j) * 2];
        p0 = fmaf(h[j], w.x, p0);
        p1 = fmaf(h[j], w.y, p1);
    }
    #pragma unroll
    for (int o = 16; o; o >>= 1) {
        p0 += __shfl_xor_sync(0xffffffffu, p0, o);
        p1 += __shfl_xor_sync(0xffffffffu, p1, o);
    }
    if (lane == 0) *(float2*)&g_h2[n * 2] = make_float2(p0, p1);
}

// ---------------- agg2 + bias -> out ----------------
__global__ __launch_bounds__(256) void k_agg2(const float* __restrict__ b2,
                                              float* __restrict__ out) {
    int warp = (blockIdx.x * blockDim.x + threadIdx.x) >> 5;
    int lane = threadIdx.x & 31;
    if (warp >= N_NODES) return;
    int beg = g_off[warp];
    int end = g_off[warp + 1];
    const int*   __restrict__ csr_src  = g_csr_src;
    const float* __restrict__ csr_norm = g_csr_norm;
    const float* __restrict__ h2       = g_h2;
    float a0 = 0.f, a1 = 0.f;
    for (int i = beg + lane; i < end; i += 32) {
        int s    = csr_src[i];
        float nm = csr_norm[i];
        float2 v = *(const float2*)&h2[s * 2];
        a0 = fmaf(v.x, nm, a0);
        a1 = fmaf(v.y, nm, a1);
    }
    #pragma unroll
    for (int o = 16; o; o >>= 1) {
        a0 += __shfl_xor_sync(0xffffffffu, a0, o);
        a1 += __shfl_xor_sync(0xffffffffu, a1, o);
    }
    if (lane == 0) {
        out[warp * 2 + 0] = a0 + b2[0];
        out[warp * 2 + 1] = a1 + b2[1];
    }
}

// ---------------- launch ----------------
extern "C" void kernel_launch(void* const* d_in, const int* in_sizes, int n_in,
                              void* d_out, int out_size) {
    const float* x   = nullptr;
    const float* W1  = nullptr;
    const float* b1  = nullptr;
    const float* W2  = nullptr;
    const float* b2  = nullptr;
    const void*  ei  = nullptr;
    int ei_elems = 0;
    for (int i = 0; i < n_in; i++) {
        switch (in_sizes[i]) {
            case 50000000: x  = (const float*)d_in[i]; break;
            case 256000:   W1 = (const float*)d_in[i]; break;
            case 256:      b1 = (const float*)d_in[i]; break;
            case 512:      W2 = (const float*)d_in[i]; break;
            case 2:        b2 = (const float*)d_in[i]; break;
            case 3200000:  ei = d_in[i]; ei_elems = in_sizes[i]; break;
            default: break;
        }
    }
    float* out = (float*)d_out;
    const int E = ei_elems / 2;
    const int SCAN_BLOCKS = (N_NODES + 1023) / 1024;
    const int N4 = N_NODES * IN_DIM / 4;
    const int NB_HIST = (E + 255) / 256;

    k_detect<<<1, 256>>>((const int*)ei, ei_elems);
    k_zero_deg<<<(N_NODES + 255) / 256, 256>>>();
    int prep_blocks = NB_HIST + NBI + NBW + NBX;
    k_prep<<<prep_blocks, 256>>>((const float4*)x, N4, W1, ei, E, NB_HIST);
    k_s1<<<SCAN_BLOCKS, 1024>>>();
    k_s3<<<SCAN_BLOCKS, 1024>>>(SCAN_BLOCKS);
    int fill_blocks = (E + N_NODES + 255) / 256;
    k_gemm1f<<<GEMM_BLOCKS + fill_blocks, 256>>>(ei, E);
    int warps_blocks = (N_NODES * 32 + 255) / 256;
    k_agg1f<<<warps_blocks, 256>>>(b1, W2);
    k_agg2<<<warps_blocks, 256>>>(b2, out);
}